// round 15
// baseline (speedup 1.0000x reference)
#include <cuda_runtime.h>
#include <cuda_bf16.h>
#include <math.h>
#include <stdint.h>

#define T_STEPS 12
#define NN      10000
#define NE      320000
#define IN_DIM  64
#define HID     128
#define EMB     64
#define G3      192             // 3*EMB
#define FTOT    (T_STEPS*EMB)   // 768
#define NROWS   (NN*T_STEPS)    // 120000
#define NROWSP  120064
#define GNODES  32
#define NNP     10112           // 79*128

typedef unsigned long long u64t;

// ---------------- scratch ----------------
__device__ float d_dinv[NN];
__device__ int   d_cnt[NN];
__device__ int   d_off[NN+1];
__device__ int   d_fill[NN];
__device__ int   d_src[NE];
__device__ float d_w[NE];
__device__ float d_AX[(size_t)NROWSP*IN_DIM];
__device__ float d_H1[(size_t)NROWSP*HID];
__device__ float d_H2[(size_t)NROWSP*EMB];
__device__ float d_Z [(size_t)NROWSP*EMB];
__device__ u64t  d_WtIH2[EMB*G3];              // W_ih^T pre-dup {w,w}
__device__ u64t  d_WtHH2[EMB*G3];              // W_hh^T pre-dup {w,w}
__device__ __nv_bfloat16 d_Za[(size_t)NNP*EMB];   // hi part of z (padding stays 0)
__device__ __nv_bfloat16 d_Zb[(size_t)NNP*EMB];   // lo part of z

// ---------------- asm helpers ----------------
static __device__ __forceinline__ uint32_t s2u(const void* p) {
    uint32_t a;
    asm("{ .reg .u64 t; cvta.to.shared.u64 t, %1; cvt.u32.u64 %0, t; }" : "=r"(a) : "l"(p));
    return a;
}
#define LDM4(r0,r1,r2,r3,addr) \
    asm volatile("ldmatrix.sync.aligned.m8n8.x4.shared.b16 {%0,%1,%2,%3}, [%4];" \
        : "=r"(r0), "=r"(r1), "=r"(r2), "=r"(r3) : "r"(addr))
#define MMA16816(c, a, b) \
    asm volatile("mma.sync.aligned.m16n8k16.row.col.f32.bf16.bf16.f32 " \
        "{%0,%1,%2,%3}, {%4,%5,%6,%7}, {%8,%9}, {%0,%1,%2,%3};" \
        : "+f"((c)[0]), "+f"((c)[1]), "+f"((c)[2]), "+f"((c)[3]) \
        : "r"((a)[0]), "r"((a)[1]), "r"((a)[2]), "r"((a)[3]), "r"((b)[0]), "r"((b)[1]))
#define FMA2(c, a, b) asm("fma.rn.f32x2 %0, %1, %2, %0;" : "+l"(c) : "l"(a), "l"(b))
#define PACK2(d, lo, hi) asm("mov.b64 %0, {%1, %2};" : "=l"(d) : "f"(lo), "f"(hi))
#define UNPACK2(lo, hi, s) asm("mov.b64 {%0, %1}, %2;" : "=f"(lo), "=f"(hi) : "l"(s))

// ---------------- preprocessing ----------------
__global__ void k_init() {
    int i = blockIdx.x*blockDim.x + threadIdx.x;
    if (i < NN) { d_dinv[i] = 1.0f; d_cnt[i] = 0; }
}

__global__ void k_deg_hist(const int* __restrict__ ei, const float* __restrict__ ew) {
    int e = blockIdx.x*blockDim.x + threadIdx.x;
    if (e >= NE) return;
    int c = ei[NE + e];
    atomicAdd(&d_dinv[c], ew[e]);
    atomicAdd(&d_cnt[c], 1);
}

// scan + rsqrt + packed weight transpose fused
__global__ void k_scan(const float* __restrict__ W_ih, const float* __restrict__ W_hh) {
    __shared__ int warpsum[32];
    int tid = threadIdx.x;
    int vals[10];
    int s = 0;
    #pragma unroll
    for (int i = 0; i < 10; i++) {
        int idx = tid*10 + i;
        int v = (idx < NN) ? d_cnt[idx] : 0;
        vals[i] = s;
        s += v;
    }
    int lane = tid & 31, wid = tid >> 5;
    int tot = s;
    #pragma unroll
    for (int o = 1; o < 32; o <<= 1) {
        int n = __shfl_up_sync(0xffffffffu, tot, o);
        if (lane >= o) tot += n;
    }
    if (lane == 31) warpsum[wid] = tot;
    __syncthreads();
    if (wid == 0) {
        int w = warpsum[lane];
        #pragma unroll
        for (int o = 1; o < 32; o <<= 1) {
            int n = __shfl_up_sync(0xffffffffu, w, o);
            if (lane >= o) w += n;
        }
        warpsum[lane] = w;
    }
    __syncthreads();
    int base = tot - s + (wid ? warpsum[wid-1] : 0);
    #pragma unroll
    for (int i = 0; i < 10; i++) {
        int idx = tid*10 + i;
        if (idx < NN) {
            int o = base + vals[i];
            d_off[idx] = o; d_fill[idx] = o;
            d_dinv[idx] = rsqrtf(d_dinv[idx]);
        }
    }
    if (tid == 1023) d_off[NN] = base + s;
    // transpose + duplicate GRU weights
    for (int i = tid; i < G3*EMB; i += 1024) {
        int j = i >> 6, k = i & 63;
        float wa = W_ih[i], wb = W_hh[i];
        u64t pa, pb;
        PACK2(pa, wa, wa); PACK2(pb, wb, wb);
        d_WtIH2[k*G3 + j] = pa;
        d_WtHH2[k*G3 + j] = pb;
    }
}

__global__ void k_scatter(const int* __restrict__ ei, const float* __restrict__ ew) {
    int e = blockIdx.x*blockDim.x + threadIdx.x;
    if (e >= NE) return;
    int r = ei[e];
    int c = ei[NE + e];
    float nm = d_dinv[r] * ew[e] * d_dinv[c];
    int pos = atomicAdd(&d_fill[c], 1);
    d_src[pos] = r;
    d_w[pos]   = nm;
}

// ---------------- batched SpMM: AX = Â X (float4/thread, 192 thr/node) ----------------
__global__ void __launch_bounds__(192)
k_spmmX(const float* __restrict__ X) {
    int d = blockIdx.x;
    int j4 = threadIdx.x;               // 0..191
    int t = j4 >> 4, kq = j4 & 15;      // feat quad
    const float4* Xt = (const float4*)(X + (size_t)t*NN*IN_DIM) + kq;  // row n -> +n*16
    float di = d_dinv[d];
    float s2 = di*di;
    float4 x = Xt[(size_t)d*16];
    float4 acc = make_float4(s2*x.x, s2*x.y, s2*x.z, s2*x.w);
    int beg = d_off[d], end = d_off[d+1];
    int p = beg;
    for (; p + 4 <= end; p += 4) {
        int   s0 = d_src[p],   s1 = d_src[p+1], s2i = d_src[p+2], s3 = d_src[p+3];
        float w0 = d_w[p],     w1 = d_w[p+1],   w2 = d_w[p+2],    w3 = d_w[p+3];
        float4 x0 = Xt[(size_t)s0*16];
        float4 x1 = Xt[(size_t)s1*16];
        float4 x2 = Xt[(size_t)s2i*16];
        float4 x3 = Xt[(size_t)s3*16];
        acc.x += w0*x0.x; acc.y += w0*x0.y; acc.z += w0*x0.z; acc.w += w0*x0.w;
        acc.x += w1*x1.x; acc.y += w1*x1.y; acc.z += w1*x1.z; acc.w += w1*x1.w;
        acc.x += w2*x2.x; acc.y += w2*x2.y; acc.z += w2*x2.z; acc.w += w2*x2.w;
        acc.x += w3*x3.x; acc.y += w3*x3.y; acc.z += w3*x3.z; acc.w += w3*x3.w;
    }
    for (; p < end; p++) {
        float w = d_w[p];
        float4 xv = Xt[(size_t)d_src[p]*16];
        acc.x += w*xv.x; acc.y += w*xv.y; acc.z += w*xv.z; acc.w += w*xv.w;
    }
    ((float4*)d_AX)[(size_t)(d*T_STEPS + t)*16 + kq] = acc;
}

// ---------------- tiled GEMM (f32x2): C = act(A@B + bias) ----------------
template<int K, int ACT>
__global__ void __launch_bounds__(256)
k_gemmT(const float* __restrict__ A, const float* __restrict__ B,
        const float* __restrict__ bias, float* __restrict__ C, int N) {
    __shared__ float As[32][132];
    __shared__ float Bs[32][64];
    int tid = threadIdx.x;
    int tr = tid >> 4, tc = tid & 15;
    int row0 = blockIdx.x * 128;
    int col0 = blockIdx.y * 64;
    u64t acc2[4][4];
    #pragma unroll
    for (int u = 0; u < 4; u++)
        #pragma unroll
        for (int v = 0; v < 4; v++) acc2[u][v] = 0ull;

    #pragma unroll
    for (int k0 = 0; k0 < K; k0 += 32) {
        #pragma unroll
        for (int p = 0; p < 4; p++) {
            int idx = p*256 + tid;
            int r = idx >> 3, k4 = (idx & 7)*4;
            float4 av = *(const float4*)&A[(size_t)(row0 + r)*K + k0 + k4];
            As[k4+0][r] = av.x; As[k4+1][r] = av.y;
            As[k4+2][r] = av.z; As[k4+3][r] = av.w;
        }
        #pragma unroll
        for (int p = 0; p < 2; p++) {
            int idx = p*256 + tid;
            int kk = idx >> 4, c4 = (idx & 15)*4;
            float4 bv = *(const float4*)&B[(size_t)(k0 + kk)*N + col0 + c4];
            *(float4*)&Bs[kk][c4] = bv;
        }
        __syncthreads();
        #pragma unroll
        for (int k = 0; k < 32; k++) {
            ulonglong2 ap0 = *(const ulonglong2*)&As[k][tr*8];
            ulonglong2 ap1 = *(const ulonglong2*)&As[k][tr*8 + 4];
            u64t aq[4] = {ap0.x, ap0.y, ap1.x, ap1.y};
            float4 b0 = *(const float4*)&Bs[k][tc*4];
            u64t bq[4];
            PACK2(bq[0], b0.x, b0.x); PACK2(bq[1], b0.y, b0.y);
            PACK2(bq[2], b0.z, b0.z); PACK2(bq[3], b0.w, b0.w);
            #pragma unroll
            for (int u = 0; u < 4; u++)
                #pragma unroll
                for (int v = 0; v < 4; v++) FMA2(acc2[u][v], aq[u], bq[v]);
        }
        __syncthreads();
    }

    float bb[4] = {0.f,0.f,0.f,0.f};
    if (bias) {
        #pragma unroll
        for (int v = 0; v < 4; v++) bb[v] = bias[col0 + tc*4 + v];
    }
    #pragma unroll
    for (int u = 0; u < 4; u++) {
        float lo[4], hi[4];
        #pragma unroll
        for (int v = 0; v < 4; v++) UNPACK2(lo[v], hi[v], acc2[u][v]);
        int r = row0 + tr*8 + u*2;
        float x0, x1, x2, x3;
        x0 = lo[0]+bb[0]; x1 = lo[1]+bb[1]; x2 = lo[2]+bb[2]; x3 = lo[3]+bb[3];
        if (ACT) { x0 = fmaxf(x0,0.f); x1 = fmaxf(x1,0.f); x2 = fmaxf(x2,0.f); x3 = fmaxf(x3,0.f); }
        *(float4*)&C[(size_t)r*N + col0 + tc*4] = make_float4(x0,x1,x2,x3);
        x0 = hi[0]+bb[0]; x1 = hi[1]+bb[1]; x2 = hi[2]+bb[2]; x3 = hi[3]+bb[3];
        if (ACT) { x0 = fmaxf(x0,0.f); x1 = fmaxf(x1,0.f); x2 = fmaxf(x2,0.f); x3 = fmaxf(x3,0.f); }
        *(float4*)&C[(size_t)(r+1)*N + col0 + tc*4] = make_float4(x0,x1,x2,x3);
    }
}

// ---------------- batched SpMM: Z = Â H2 + b2 (float4/thread) ----------------
__global__ void __launch_bounds__(192)
k_spmmZ(const float* __restrict__ b2) {
    int d = blockIdx.x;
    int j4 = threadIdx.x;               // 0..191
    int t = j4 >> 4, kq = j4 & 15;
    const float4* H = (const float4*)d_H2 + (size_t)t*16 + kq;  // row n -> +n*T*16
    float di = d_dinv[d];
    float s2 = di*di;
    float4 x = H[(size_t)d*T_STEPS*16];
    float4 acc = make_float4(s2*x.x, s2*x.y, s2*x.z, s2*x.w);
    int beg = d_off[d], end = d_off[d+1];
    int p = beg;
    for (; p + 4 <= end; p += 4) {
        int   s0 = d_src[p],   s1 = d_src[p+1], s2i = d_src[p+2], s3 = d_src[p+3];
        float w0 = d_w[p],     w1 = d_w[p+1],   w2 = d_w[p+2],    w3 = d_w[p+3];
        float4 x0 = H[(size_t)s0*T_STEPS*16];
        float4 x1 = H[(size_t)s1*T_STEPS*16];
        float4 x2 = H[(size_t)s2i*T_STEPS*16];
        float4 x3 = H[(size_t)s3*T_STEPS*16];
        acc.x += w0*x0.x; acc.y += w0*x0.y; acc.z += w0*x0.z; acc.w += w0*x0.w;
        acc.x += w1*x1.x; acc.y += w1*x1.y; acc.z += w1*x1.z; acc.w += w1*x1.w;
        acc.x += w2*x2.x; acc.y += w2*x2.y; acc.z += w2*x2.z; acc.w += w2*x2.w;
        acc.x += w3*x3.x; acc.y += w3*x3.y; acc.z += w3*x3.z; acc.w += w3*x3.w;
    }
    for (; p < end; p++) {
        float w = d_w[p];
        float4 xv = H[(size_t)d_src[p]*T_STEPS*16];
        acc.x += w*xv.x; acc.y += w*xv.y; acc.z += w*xv.z; acc.w += w*xv.w;
    }
    float4 bv = *((const float4*)b2 + kq);
    acc.x += bv.x; acc.y += bv.y; acc.z += bv.z; acc.w += bv.w;
    ((float4*)d_Z)[(size_t)(d*T_STEPS + t)*16 + kq] = acc;
}

// ---------------- fused GRU (f32x2, pre-dup weights) + bf16 split epilogue ----------------
__global__ void __launch_bounds__(256)
k_gruF(const float* __restrict__ b_ih, const float* __restrict__ b_hh,
       float* __restrict__ out) {
    __shared__ float hs[64][GNODES+4];
    __shared__ float zs[64][GNODES+4];
    int tid = threadIdx.x;
    int j = tid & 63;
    int g = tid >> 6;
    int nlo = g * 8;
    int nb = blockIdx.x * GNODES;

    for (int idx = tid; idx < 64*GNODES; idx += 256) {
        int m = idx >> 6, k = idx & 63;
        hs[k][m] = 0.f;
    }

    float br = b_hh[j],     bz = b_hh[64+j],  bn = b_hh[128+j];
    float cr = b_ih[j],     cz = b_ih[64+j],  cn = b_ih[128+j];

    for (int t = 0; t < T_STEPS; t++) {
        __syncthreads();
        for (int idx = tid; idx < 64*GNODES; idx += 256) {
            int m = idx >> 6, k = idx & 63;
            int node = nb + m;
            zs[k][m] = (node < NN) ? d_Z[(size_t)node*FTOT + t*EMB + k] : 0.f;
        }
        __syncthreads();

        u64t ir2[4], iz2[4], in2[4], hr2[4], hz2[4], hn2[4];
        #pragma unroll
        for (int m = 0; m < 4; m++) { ir2[m]=iz2[m]=in2[m]=hr2[m]=hz2[m]=hn2[m]=0ull; }

        #pragma unroll 4
        for (int k = 0; k < EMB; k++) {
            const u64t* wi2 = &d_WtIH2[k*G3];
            const u64t* wh2 = &d_WtHH2[k*G3];
            u64t wir2 = wi2[j], wiz2 = wi2[64+j], win2 = wi2[128+j];
            u64t whr2 = wh2[j], whz2 = wh2[64+j], whn2 = wh2[128+j];
            ulonglong2 zp0 = *(const ulonglong2*)&zs[k][nlo];
            ulonglong2 zp1 = *(const ulonglong2*)&zs[k][nlo+4];
            ulonglong2 hp0 = *(const ulonglong2*)&hs[k][nlo];
            ulonglong2 hp1 = *(const ulonglong2*)&hs[k][nlo+4];
            u64t zq[4] = {zp0.x, zp0.y, zp1.x, zp1.y};
            u64t hq[4] = {hp0.x, hp0.y, hp1.x, hp1.y};
            #pragma unroll
            for (int m = 0; m < 4; m++) {
                FMA2(ir2[m], zq[m], wir2);
                FMA2(iz2[m], zq[m], wiz2);
                FMA2(in2[m], zq[m], win2);
                FMA2(hr2[m], hq[m], whr2);
                FMA2(hz2[m], hq[m], whz2);
                FMA2(hn2[m], hq[m], whn2);
            }
        }
        float ir[8], iz[8], inx[8], hr[8], hz[8], hn[8];
        #pragma unroll
        for (int m = 0; m < 4; m++) {
            UNPACK2(ir[2*m],  ir[2*m+1],  ir2[m]);
            UNPACK2(iz[2*m],  iz[2*m+1],  iz2[m]);
            UNPACK2(inx[2*m], inx[2*m+1], in2[m]);
            UNPACK2(hr[2*m],  hr[2*m+1],  hr2[m]);
            UNPACK2(hz[2*m],  hz[2*m+1],  hz2[m]);
            UNPACK2(hn[2*m],  hn[2*m+1],  hn2[m]);
        }
        __syncthreads();
        #pragma unroll
        for (int m = 0; m < 8; m++) {
            float r  = 1.f/(1.f + __expf(-(ir[m] + cr + hr[m] + br)));
            float zg = 1.f/(1.f + __expf(-(iz[m] + cz + hz[m] + bz)));
            float ng = tanhf(inx[m] + cn + r*(hn[m] + bn));
            float ho = hs[j][nlo + m];
            hs[j][nlo + m] = (1.f - zg)*ng + zg*ho;
        }
    }
    __syncthreads();
    for (int idx = tid; idx < 64*GNODES; idx += 256) {
        int m = idx >> 6, k = idx & 63;
        int node = nb + m;
        if (node < NN) {
            float v = hs[k][m];
            out[(size_t)NN*NN + (size_t)node*EMB + k] = v;
            __nv_bfloat16 a = __float2bfloat16(v);
            d_Za[(size_t)node*EMB + k] = a;
            d_Zb[(size_t)node*EMB + k] = __float2bfloat16(v - __bfloat162float(a));
        }
    }
}

// ---------------- mma.sync decoder: softplus(z z^T + b), symmetric ----------------
#define TS_B    144
#define TILE_B  (128*TS_B)
#define DEC_SMEM (4*TILE_B)
__global__ void __launch_bounds__(256)
k_dectc(float* __restrict__ out, const float* __restrict__ db) {
    int bi = blockIdx.y, bj = blockIdx.x;
    if (bi > bj) return;
    extern __shared__ __align__(16) char smem[];
    uint32_t sb = s2u(smem);
    uint32_t* sm32 = (uint32_t*)smem;
    float* stage = (float*)smem;

    int tid = threadIdx.x;
    int wid = tid >> 5, lane = tid & 31;
    int wm = wid >> 2, wn = wid & 3;

    int i0 = bi*128, j0 = bj*128;
    const uint32_t* za32 = (const uint32_t*)d_Za;
    const uint32_t* zb32 = (const uint32_t*)d_Zb;

    for (int idx = tid; idx < 4096; idx += 256) {
        int r = idx >> 5, c = idx & 31;
        int base = r*36 + c;
        sm32[base]                 = za32[(size_t)(i0+r)*32 + c];
        sm32[base + TILE_B/4]      = zb32[(size_t)(i0+r)*32 + c];
        sm32[base + 2*(TILE_B/4)]  = za32[(size_t)(j0+r)*32 + c];
        sm32[base + 3*(TILE_B/4)]  = zb32[(size_t)(j0+r)*32 + c];
    }
    __syncthreads();

    float acc[4][4][4];
    #pragma unroll
    for (int mf = 0; mf < 4; mf++)
        #pragma unroll
        for (int nf = 0; nf < 4; nf++)
            #pragma unroll
            for (int q = 0; q < 4; q++) acc[mf][nf][q] = 0.f;

    uint32_t aRow = wm*64 + (lane & 15);
    uint32_t aKb  = (lane >> 4) * 16;
    uint32_t bRow = wn*32 + (lane & 7) + ((lane >> 4) << 3);
    uint32_t bKb  = ((lane >> 3) & 1) * 16;

    uint32_t adAa = sb + aRow*TS_B + aKb;
    uint32_t adAb = adAa + TILE_B;
    uint32_t adBa = sb + 2*TILE_B + bRow*TS_B + bKb;
    uint32_t adBb = adBa + TILE_B;

    #pragma unroll
    for (int ks = 0; ks < 4; ks++) {
        uint32_t kof = ks*32;
        uint32_t Aa[4][4], Ab[4][4], Ba[4][2], Bb[4][2];
        #pragma unroll
        for (int mf = 0; mf < 4; mf++) {
            LDM4(Aa[mf][0], Aa[mf][1], Aa[mf][2], Aa[mf][3], adAa + mf*16*TS_B + kof);
            LDM4(Ab[mf][0], Ab[mf][1], Ab[mf][2], Ab[mf][3], adAb + mf*16*TS_B + kof);
        }
        #pragma unroll
        for (int np = 0; np < 2; np++) {
            LDM4(Ba[np*2][0], Ba[np*2][1], Ba[np*2+1][0], Ba[np*2+1][1], adBa + np*16*TS_B + kof);
            LDM4(Bb[np*2][0], Bb[np*2][1], Bb[np*2+1][0], Bb[np*2+1][1], adBb + np*16*TS_B + kof);
        }
        #pragma unroll
        for (int mf = 0; mf < 4; mf++)
            #pragma unroll
            for (int nf = 0; nf < 4; nf++) {
                MMA16816(acc[mf][nf], Aa[mf], Ba[nf]);
                MMA16816(acc[mf][nf], Aa[mf], Bb[nf]);
                MMA16816(acc[mf][nf], Ab[mf], Ba[nf]);
            }
    }
    __syncthreads();

    float bias = db[0];
    bool diag = (bi == bj);
    int l4 = lane >> 2, l2 = (lane & 3) * 2;

    #pragma unroll
    for (int h = 0; h < 2; h++) {
        if ((wn >> 1) == h) {
            int cb = (wn & 1)*32;
            #pragma unroll
            for (int mf = 0; mf < 4; mf++) {
                int rB = wm*64 + mf*16 + l4;
                #pragma unroll
                for (int nf = 0; nf < 4; nf++) {
                    int cB = cb + nf*8 + l2;
                    #pragma unroll
                    for (int q = 0; q < 4; q++) {
                        float x = acc[mf][nf][q] + bias;
                        x = fmaxf(x, 0.f) + __logf(1.f + __expf(-fabsf(x)));
                        int rr = rB + ((q >> 1) << 3);
                        int cc = cB + (q & 1);
                        stage[rr*65 + cc] = x;
                    }
                }
            }
        }
        __syncthreads();
        for (int idx = tid; idx < 8192; idx += 256) {
            int c = idx & 63, r = idx >> 6;
            int gi = i0 + r, gj = j0 + h*64 + c;
            if (gi < NN && gj < NN) out[(size_t)gi*NN + gj] = stage[r*65 + c];
        }
        if (!diag) {
            for (int idx = tid; idx < 8192; idx += 256) {
                int r = idx & 127, c = idx >> 7;
                int gi = i0 + r, gj = j0 + h*64 + c;
                if (gi < NN && gj < NN) out[(size_t)gj*NN + gi] = stage[r*65 + c];
            }
        }
        __syncthreads();
    }
}

// ---------------- launch ----------------
extern "C" void kernel_launch(void* const* d_in, const int* in_sizes, int n_in,
                              void* d_out, int out_size) {
    const float* x_seq = (const float*)d_in[0];
    const int*   ei    = (const int*)d_in[1];
    const float* ew    = (const float*)d_in[2];
    const float* W1    = (const float*)d_in[3];
    const float* b1    = (const float*)d_in[4];
    const float* W2    = (const float*)d_in[5];
    const float* b2    = (const float*)d_in[6];
    const float* W_ih  = (const float*)d_in[7];
    const float* W_hh  = (const float*)d_in[8];
    const float* b_ih  = (const float*)d_in[9];
    const float* b_hh  = (const float*)d_in[10];
    const float* dbias = (const float*)d_in[11];
    float* out = (float*)d_out;

    float *pAX, *pH1, *pH2;
    cudaGetSymbolAddress((void**)&pAX, d_AX);
    cudaGetSymbolAddress((void**)&pH1, d_H1);
    cudaGetSymbolAddress((void**)&pH2, d_H2);

    cudaFuncSetAttribute(k_dectc, cudaFuncAttributeMaxDynamicSharedMemorySize, DEC_SMEM);

    // preprocessing
    k_init<<<(NN + 255)/256, 256>>>();
    k_deg_hist<<<(NE + 255)/256, 256>>>(ei, ew);
    k_scan<<<1, 1024>>>(W_ih, W_hh);
    k_scatter<<<(NE + 255)/256, 256>>>(ei, ew);

    // encoder
    k_spmmX<<<NN, 192>>>(x_seq);
    k_gemmT<IN_DIM, 1><<<dim3(NROWSP/128, 2), 256>>>(pAX, W1, b1, pH1, HID);
    k_gemmT<HID,    0><<<dim3(NROWSP/128, 1), 256>>>(pH1, W2, nullptr, pH2, EMB);
    k_spmmZ<<<NN, 192>>>(b2);

    // fused GRU (writes output tail + bf16 split directly)
    k_gruF<<<(NN + GNODES - 1)/GNODES, 256>>>(b_ih, b_hh, out);

    // decoder: bf16-split mma.sync GEMM, symmetric
    const int NT = NNP/128;   // 79
    k_dectc<<<dim3(NT, NT), 256, DEC_SMEM>>>(out, dbias);
}